// round 6
// baseline (speedup 1.0000x reference)
#include <cuda_runtime.h>
#include <math.h>

#define N_PART   16384
#define DDIM     16
#define PDIM     8
#define M_STEPS  50
#define HDIM     128
#define IN_DIM   25        // 1 + D + P
#define BLK_P    128       // particles per CTA
#define NTHREADS 256
#define LDIN     25        // sIn row stride (odd -> conflict-free column access)
#define LDH      132       // sH row stride (mult of 4 for vector ld/st)

typedef unsigned long long u64;

static __device__ __forceinline__ u64 pack2(float x, float y) {
    u64 r;
    asm("mov.b64 %0, {%1, %2};" : "=l"(r) : "f"(x), "f"(y));
    return r;
}
static __device__ __forceinline__ u64 fma2(u64 a, u64 b, u64 c) {
    u64 d;
    asm("fma.rn.f32x2 %0, %1, %2, %3;" : "=l"(d) : "l"(a), "l"(b), "l"(c));
    return d;
}
static __device__ __forceinline__ float2 unpack2(u64 v) {
    float2 f;
    asm("mov.b64 {%0, %1}, %2;" : "=f"(f.x), "=f"(f.y) : "l"(v));
    return f;
}

// C[8x8] tile (as 8x4 f32x2) += A[row0..row0+8, 0..K) * B[0..K, col0..col0+8)
// A: row stride LDA (floats).  B: row stride LDB (floats), col0 8-float (32B) aligned.
template <int K, int LDA, int LDB>
static __device__ __forceinline__ void mm_tile(const float* __restrict__ A,
                                               const float* __restrict__ B,
                                               int row0, int col0,
                                               u64 c[8][4]) {
#pragma unroll 4
    for (int k = 0; k < K; k++) {
        const u64* br = (const u64*)(B + k * LDB + col0);
        u64 b0 = br[0], b1 = br[1], b2 = br[2], b3 = br[3];
        const float* ac = A + row0 * LDA + k;
#pragma unroll
        for (int i = 0; i < 8; i++) {
            float av = ac[i * LDA];
            u64 a2 = pack2(av, av);
            c[i][0] = fma2(a2, b0, c[i][0]);
            c[i][1] = fma2(a2, b1, c[i][1]);
            c[i][2] = fma2(a2, b2, c[i][2]);
            c[i][3] = fma2(a2, b3, c[i][3]);
        }
    }
}

static __device__ __forceinline__ void store_relu_bias(float* __restrict__ dst,
                                                       int row0, int col0,
                                                       const u64 c[8][4],
                                                       const float* __restrict__ bias) {
#pragma unroll
    for (int i = 0; i < 8; i++) {
        float2* drow = (float2*)(dst + (row0 + i) * LDH + col0);
#pragma unroll
        for (int j = 0; j < 4; j++) {
            float2 v = unpack2(c[i][j]);
            v.x = fmaxf(v.x + bias[col0 + 2 * j + 0], 0.0f);
            v.y = fmaxf(v.y + bias[col0 + 2 * j + 1], 0.0f);
            drow[j] = v;
        }
    }
}

__global__ void __launch_bounds__(NTHREADS, 1)
sde_rollout_kernel(const float* __restrict__ X0, const float* __restrict__ V0,
                   const float* __restrict__ obs, const float* __restrict__ noise,
                   const float* __restrict__ W1, const float* __restrict__ b1,
                   const float* __restrict__ W2, const float* __restrict__ b2,
                   const float* __restrict__ W3, const float* __restrict__ b3,
                   float* __restrict__ out) {
    extern __shared__ float sm[];
    float* W1s = sm;                        // 25*128 = 3200
    float* b1s = W1s + IN_DIM * HDIM;       // 128
    float* W2s = b1s + HDIM;                // 128*128 = 16384
    float* b2s = W2s + HDIM * HDIM;         // 128
    float* W3s = b2s + HDIM;                // 128*16 = 2048
    float* b3s = W3s + HDIM * DDIM;         // 16
    float* sIn = b3s + 16;                  // 128*25 = 3200   (offset 21904, 16B aligned)
    float* sH  = sIn + BLK_P * LDIN;        // 128*132 = 16896
    float* sV  = sH + BLK_P * LDH;          // 128

    const int tid = threadIdx.x;
    const int pbase = blockIdx.x * BLK_P;

    // ---- cooperative weight load ----
    for (int i = tid; i < (IN_DIM * HDIM) / 4; i += NTHREADS)
        ((float4*)W1s)[i] = ((const float4*)W1)[i];
    for (int i = tid; i < (HDIM * HDIM) / 4; i += NTHREADS)
        ((float4*)W2s)[i] = ((const float4*)W2)[i];
    for (int i = tid; i < (HDIM * DDIM) / 4; i += NTHREADS)
        ((float4*)W3s)[i] = ((const float4*)W3)[i];
    if (tid < HDIM) { b1s[tid] = b1[tid]; b2s[tid] = b2[tid]; }
    if (tid < DDIM) b3s[tid] = b3[tid];

    // ---- init particle state: sIn row = [t, X(16), obs(8)], sV ----
    const int p  = tid >> 1;
    const int dh = (tid & 1) * 8;
    const int pg = pbase + p;
    {
        float4 xa = *(const float4*)(X0 + (size_t)pg * DDIM + dh);
        float4 xb = *(const float4*)(X0 + (size_t)pg * DDIM + dh + 4);
        float* row = sIn + p * LDIN;
        row[1 + dh + 0] = xa.x; row[1 + dh + 1] = xa.y;
        row[1 + dh + 2] = xa.z; row[1 + dh + 3] = xa.w;
        row[1 + dh + 4] = xb.x; row[1 + dh + 5] = xb.y;
        row[1 + dh + 6] = xb.z; row[1 + dh + 7] = xb.w;
        if ((tid & 1) == 0) {
            row[0] = 0.0f;                 // t = times[0] = 0
            sV[p] = V0[pg];
#pragma unroll
            for (int j = 0; j < PDIM; j++)
                row[1 + DDIM + j] = obs[(size_t)pg * PDIM + j];
        }
    }
    __syncthreads();

    const float dt   = (float)(1.0 / (double)M_STEPS);  // T = 1
    const float sqdt = sqrtf(dt);
    const int ty = tid >> 4, tx = tid & 15;
    const int row0 = ty * 8, col0 = tx * 8;

    for (int m = 0; m < M_STEPS; m++) {
        // ---- layer 1: h1 = relu(In @ W1 + b1) ----
        u64 c[8][4];
#pragma unroll
        for (int i = 0; i < 8; i++) { c[i][0]=0; c[i][1]=0; c[i][2]=0; c[i][3]=0; }
        mm_tile<IN_DIM, LDIN, HDIM>(sIn, W1s, row0, col0, c);
        store_relu_bias(sH, row0, col0, c, b1s);   // sH free (prev step fenced)
        __syncthreads();

        // ---- layer 2: h2 = relu(h1 @ W2 + b2) ----
#pragma unroll
        for (int i = 0; i < 8; i++) { c[i][0]=0; c[i][1]=0; c[i][2]=0; c[i][3]=0; }
        mm_tile<HDIM, LDH, HDIM>(sH, W2s, row0, col0, c);
        __syncthreads();                            // everyone done reading h1
        store_relu_bias(sH, row0, col0, c, b2s);
        __syncthreads();

        // ---- layer 3: Z = h2 @ W3 + b3 ; V,X update (2 threads per particle) ----
        u64 cz[4] = {0, 0, 0, 0};
        const float* hrow = sH + p * LDH;
#pragma unroll 8
        for (int k = 0; k < HDIM; k++) {
            float hv = hrow[k];
            u64 a2 = pack2(hv, hv);
            const u64* wr = (const u64*)(W3s + k * DDIM + dh);
            cz[0] = fma2(a2, wr[0], cz[0]);
            cz[1] = fma2(a2, wr[1], cz[1]);
            cz[2] = fma2(a2, wr[2], cz[2]);
            cz[3] = fma2(a2, wr[3], cz[3]);
        }
        float z[8];
#pragma unroll
        for (int j4 = 0; j4 < 4; j4++) {
            float2 v = unpack2(cz[j4]);
            z[2 * j4 + 0] = v.x + b3s[dh + 2 * j4 + 0];
            z[2 * j4 + 1] = v.y + b3s[dh + 2 * j4 + 1];
        }
        // Brownian increment for my 8 dims
        const float* np = noise + (((size_t)m * N_PART + pg) * DDIM + dh);
        float4 e0 = *(const float4*)np;
        float4 e1 = *(const float4*)(np + 4);
        float eps[8] = {e0.x, e0.y, e0.z, e0.w, e1.x, e1.y, e1.z, e1.w};

        float zz = 0.0f, zw = 0.0f;
#pragma unroll
        for (int j = 0; j < 8; j++) {
            zz = fmaf(z[j], z[j], zz);
            zw = fmaf(z[j], sqdt * eps[j], zw);
        }
        zz += __shfl_xor_sync(0xffffffffu, zz, 1);
        zw += __shfl_xor_sync(0xffffffffu, zw, 1);

        // X <- X*(1-dt) + sqrt(dt)*eps   (sigma = 1)
        float* xr = sIn + p * LDIN + 1 + dh;
#pragma unroll
        for (int j = 0; j < 8; j++)
            xr[j] = fmaf(xr[j], 1.0f - dt, sqdt * eps[j]);

        if ((tid & 1) == 0) {
            sV[p] = sV[p] + dt * 0.5f * zz + zw;     // V update
            sIn[p * LDIN] = (float)(m + 1) * dt;     // t for next step
        }
        __syncthreads();
    }

    // ---- write outputs: X (N*16) then V (N) ----
    {
        float* xo = out + (size_t)pg * DDIM + dh;
        const float* xr = sIn + p * LDIN + 1 + dh;
#pragma unroll
        for (int j = 0; j < 8; j++) xo[j] = xr[j];
        if ((tid & 1) == 0) out[(size_t)N_PART * DDIM + pg] = sV[p];
    }
}

extern "C" void kernel_launch(void* const* d_in, const int* in_sizes, int n_in,
                              void* d_out, int out_size) {
    const float* X0    = (const float*)d_in[0];
    const float* V0    = (const float*)d_in[1];
    const float* obs   = (const float*)d_in[2];
    const float* noise = (const float*)d_in[3];
    const float* W1    = (const float*)d_in[4];
    const float* b1    = (const float*)d_in[5];
    const float* W2    = (const float*)d_in[6];
    const float* b2    = (const float*)d_in[7];
    const float* W3    = (const float*)d_in[8];
    const float* b3    = (const float*)d_in[9];
    float* out = (float*)d_out;

    const size_t smem_bytes =
        (size_t)(IN_DIM * HDIM + HDIM + HDIM * HDIM + HDIM + HDIM * DDIM + 16 +
                 BLK_P * LDIN + BLK_P * LDH + BLK_P) * sizeof(float);

    cudaFuncSetAttribute(sde_rollout_kernel,
                         cudaFuncAttributeMaxDynamicSharedMemorySize,
                         (int)smem_bytes);

    sde_rollout_kernel<<<N_PART / BLK_P, NTHREADS, smem_bytes>>>(
        X0, V0, obs, noise, W1, b1, W2, b2, W3, b3, out);
}